// round 8
// baseline (speedup 1.0000x reference)
#include <cuda_runtime.h>

// Modelev12: 2-layer LSTM, H=48, B=4096, T=512, F=64
// R7: warp-independent (R6) + duplicated-h layout (kills pack MOVs) +
// load-front-loaded inner loop for intra-warp latency hiding.
#define H      48
#define TOBS   512
#define FPRED  64
#define TTOT   (TOBS + FPRED)     // 576
#define BATCH  4096
#define MB     32                 // batch rows per CTA
#define NCTA   (BATCH / MB)       // 128
#define NTHR   256                // 8 warps x 4 batches each

typedef unsigned long long ull;

// float-offset shared layout (16B alignment everywhere it matters)
#define OFF_WTP0 0                       // ull[48*96]  {W[q][k], W[q+96][k]}
#define OFF_WTP1 9216                    // ull[96*96]
#define OFF_WI0P 27648                   // ull[96]
#define OFF_B0P  27840                   // ull[96]
#define OFF_B1P  28032                   // ull[96]
#define OFF_HW2  28224                   // 8 warps x ull[96*4]  {h,h} per (k,b)
#define OFF_XCW  (OFF_HW2 + 8*768)       // 8 warps x ull[4] (+pad) {x,x}
#define OFF_GTP  (OFF_XCW + 8*16)        // 8 warps x 4*GSTR ull gate pairs
#define GSTR     101                     // ull stride per batch in gate buffer
#define GWARP    (4 * GSTR)
#define SMEM_FLOATS (OFF_GTP + 8 * 2 * GWARP)
#define SMEM_BYTES  (SMEM_FLOATS * 4)    // ~160 KB

__device__ __forceinline__ ull ffma2(ull a, ull b, ull c) {
    ull d;
    asm("fma.rn.f32x2 %0, %1, %2, %3;" : "=l"(d) : "l"(a), "l"(b), "l"(c));
    return d;
}
__device__ __forceinline__ ull pack1(float v) {            // {v, v}
    ull d; asm("mov.b64 %0, {%1, %1};" : "=l"(d) : "f"(v)); return d;
}
__device__ __forceinline__ ull pack2(float lo, float hi) {
    ull d; asm("mov.b64 %0, {%1, %2};" : "=l"(d) : "f"(lo), "f"(hi)); return d;
}
__device__ __forceinline__ float fsig(float xv) {
    float e = __expf(-xv);
    return __fdividef(1.0f, 1.0f + e);
}
__device__ __forceinline__ float ftanh(float xv) {
    float a = fabsf(xv);
    float e = __expf(-2.0f * a);
    float r = __fdividef(1.0f - e, 1.0f + e);
    return copysignf(r, xv);
}

__global__ void __launch_bounds__(NTHR, 1) lstm576_wi2_kernel(
    const float* __restrict__ x,
    const float* __restrict__ wih0, const float* __restrict__ whh0,
    const float* __restrict__ bih0, const float* __restrict__ bhh0,
    const float* __restrict__ wih1, const float* __restrict__ whh1,
    const float* __restrict__ bih1, const float* __restrict__ bhh1,
    const float* __restrict__ wlin, const float* __restrict__ blin,
    float* __restrict__ out)
{
    extern __shared__ float sm[];
    ull* WTP0 = (ull*)(sm + OFF_WTP0);
    ull* WTP1 = (ull*)(sm + OFF_WTP1);
    ull* WI0P = (ull*)(sm + OFF_WI0P);
    ull* B0P  = (ull*)(sm + OFF_B0P);
    ull* B1P  = (ull*)(sm + OFF_B1P);

    const int tid  = threadIdx.x;
    const int lane = tid & 31;
    const int w    = tid >> 5;           // warp 0..7
    const int m8   = lane & 7;           // 8-lane segment position
    const int lb   = lane >> 3;          // local batch 0..3 (act/head)
    const int gb0  = blockIdx.x * MB;
    const int gbat = gb0 + 4 * w + lb;

    ull* HW2w = (ull*)(sm + OFF_HW2) + w * 384;      // [96][4] {h,h}
    ull* XCw  = (ull*)(sm + OFF_XCW) + w * 8;        // [4] {x,x}
    ull* GTPw = (ull*)(sm + OFF_GTP) + w * GWARP;    // [4][GSTR] gate pairs

    // ---- one-time staging ----
    for (int i = tid; i < 48 * 96; i += NTHR) {
        int k = i / 96, q = i - k * 96;
        WTP0[i] = pack2(whh0[q * 48 + k], whh0[(q + 96) * 48 + k]);
    }
    for (int i = tid; i < 96 * 96; i += NTHR) {
        int k = i / 96, q = i - k * 96;
        float v0 = (k < 48) ? wih1[q * 48 + k] : whh1[q * 48 + (k - 48)];
        float v1 = (k < 48) ? wih1[(q + 96) * 48 + k] : whh1[(q + 96) * 48 + (k - 48)];
        WTP1[i] = pack2(v0, v1);
    }
    if (tid < 96) {
        WI0P[tid] = pack2(wih0[tid], wih0[tid + 96]);
        B0P[tid]  = pack2(bih0[tid] + bhh0[tid], bih0[tid + 96] + bhh0[tid + 96]);
        B1P[tid]  = pack2(bih1[tid] + bhh1[tid], bih1[tid + 96] + bhh1[tid + 96]);
    }
    for (int i = tid; i < 8 * 384; i += NTHR) ((ull*)(sm + OFF_HW2))[i] = 0ull;
    if (m8 == 0) XCw[lb] = pack1(x[(size_t)gbat * TOBS]);
    const float blv = blin[0];

    float wlr[6];
#pragma unroll
    for (int i = 0; i < 6; i++) wlr[i] = wlin[m8 * 6 + i];

    float c0r[6], c1r[6];
#pragma unroll
    for (int i = 0; i < 6; i++) { c0r[i] = 0.0f; c1r[i] = 0.0f; }

    __syncthreads();   // only block-wide sync

    ull acc[3][4];

    for (int t = 0; t < TTOT; t++) {
        float xnext = 0.0f;
        if (m8 == 0 && (t + 1) < TOBS)
            xnext = x[(size_t)gbat * TOBS + (t + 1)];

        // ============ layer 0: 192 rows x (x + 48 h0) ============
        {
            ulonglong2 xq0 = ((const ulonglong2*)XCw)[0];
            ulonglong2 xq1 = ((const ulonglong2*)XCw)[1];
            ull xx[4] = { xq0.x, xq0.y, xq1.x, xq1.y };
#pragma unroll
            for (int pp = 0; pp < 3; pp++) {
                ull wi = WI0P[32 * pp + lane];
                ull bs = B0P[32 * pp + lane];
#pragma unroll
                for (int b = 0; b < 4; b++) acc[pp][b] = ffma2(wi, xx[b], bs);
            }
#pragma unroll 4
            for (int kt = 0; kt < 48; kt += 2) {
                // all loads first: 4x LDS.128 (h, broadcast) + 6x LDS.64 (w)
                ulonglong2 hA = ((const ulonglong2*)HW2w)[kt * 2];
                ulonglong2 hB = ((const ulonglong2*)HW2w)[kt * 2 + 1];
                ulonglong2 hC = ((const ulonglong2*)HW2w)[kt * 2 + 2];
                ulonglong2 hD = ((const ulonglong2*)HW2w)[kt * 2 + 3];
                ull w0[3], w1[3];
#pragma unroll
                for (int pp = 0; pp < 3; pp++) {
                    w0[pp] = WTP0[kt * 96 + 32 * pp + lane];
                    w1[pp] = WTP0[(kt + 1) * 96 + 32 * pp + lane];
                }
#pragma unroll
                for (int pp = 0; pp < 3; pp++) {
                    acc[pp][0] = ffma2(w0[pp], hA.x, acc[pp][0]);
                    acc[pp][1] = ffma2(w0[pp], hA.y, acc[pp][1]);
                    acc[pp][2] = ffma2(w0[pp], hB.x, acc[pp][2]);
                    acc[pp][3] = ffma2(w0[pp], hB.y, acc[pp][3]);
                }
#pragma unroll
                for (int pp = 0; pp < 3; pp++) {
                    acc[pp][0] = ffma2(w1[pp], hC.x, acc[pp][0]);
                    acc[pp][1] = ffma2(w1[pp], hC.y, acc[pp][1]);
                    acc[pp][2] = ffma2(w1[pp], hD.x, acc[pp][2]);
                    acc[pp][3] = ffma2(w1[pp], hD.y, acc[pp][3]);
                }
            }
#pragma unroll
            for (int pp = 0; pp < 3; pp++)
#pragma unroll
                for (int b = 0; b < 4; b++)
                    GTPw[b * GSTR + 32 * pp + lane] = acc[pp][b];
        }
        __syncwarp();

        // ---- layer 0 activations: pair j = (i,g), pair j+48 = (f,o) ----
#pragma unroll
        for (int i = 0; i < 6; i++) {
            int j = m8 * 6 + i;
            float2 ig = *(const float2*)(GTPw + lb * GSTR + j);
            float2 fo = *(const float2*)(GTPw + lb * GSTR + 48 + j);
            float ii = fsig(ig.x), gg = ftanh(ig.y);
            float ff = fsig(fo.x), oo = fsig(fo.y);
            float c = fmaf(ff, c0r[i], ii * gg);
            c0r[i] = c;
            HW2w[j * 4 + lb] = pack1(oo * ftanh(c));
        }
        __syncwarp();

        // ============ layer 1: 192 rows x (48 h0_new + 48 h1_old) ============
        {
#pragma unroll
            for (int pp = 0; pp < 3; pp++) {
                ull bs = B1P[32 * pp + lane];
#pragma unroll
                for (int b = 0; b < 4; b++) acc[pp][b] = bs;
            }
#pragma unroll 4
            for (int kt = 0; kt < 96; kt += 2) {
                ulonglong2 hA = ((const ulonglong2*)HW2w)[kt * 2];
                ulonglong2 hB = ((const ulonglong2*)HW2w)[kt * 2 + 1];
                ulonglong2 hC = ((const ulonglong2*)HW2w)[kt * 2 + 2];
                ulonglong2 hD = ((const ulonglong2*)HW2w)[kt * 2 + 3];
                ull w0[3], w1[3];
#pragma unroll
                for (int pp = 0; pp < 3; pp++) {
                    w0[pp] = WTP1[kt * 96 + 32 * pp + lane];
                    w1[pp] = WTP1[(kt + 1) * 96 + 32 * pp + lane];
                }
#pragma unroll
                for (int pp = 0; pp < 3; pp++) {
                    acc[pp][0] = ffma2(w0[pp], hA.x, acc[pp][0]);
                    acc[pp][1] = ffma2(w0[pp], hA.y, acc[pp][1]);
                    acc[pp][2] = ffma2(w0[pp], hB.x, acc[pp][2]);
                    acc[pp][3] = ffma2(w0[pp], hB.y, acc[pp][3]);
                }
#pragma unroll
                for (int pp = 0; pp < 3; pp++) {
                    acc[pp][0] = ffma2(w1[pp], hC.x, acc[pp][0]);
                    acc[pp][1] = ffma2(w1[pp], hC.y, acc[pp][1]);
                    acc[pp][2] = ffma2(w1[pp], hD.x, acc[pp][2]);
                    acc[pp][3] = ffma2(w1[pp], hD.y, acc[pp][3]);
                }
            }
#pragma unroll
            for (int pp = 0; pp < 3; pp++)
#pragma unroll
                for (int b = 0; b < 4; b++)
                    GTPw[b * GSTR + 32 * pp + lane] = acc[pp][b];
        }
        __syncwarp();

        // ---- layer 1 activations + fused in-warp head ----
        float s = 0.0f;
#pragma unroll
        for (int i = 0; i < 6; i++) {
            int j = m8 * 6 + i;
            float2 ig = *(const float2*)(GTPw + lb * GSTR + j);
            float2 fo = *(const float2*)(GTPw + lb * GSTR + 48 + j);
            float ii = fsig(ig.x), gg = ftanh(ig.y);
            float ff = fsig(fo.x), oo = fsig(fo.y);
            float c = fmaf(ff, c1r[i], ii * gg);
            c1r[i] = c;
            float h = oo * ftanh(c);
            HW2w[(48 + j) * 4 + lb] = pack1(h);
            s = fmaf(h, wlr[i], s);
        }
        s += __shfl_xor_sync(0xFFFFFFFFu, s, 1);
        s += __shfl_xor_sync(0xFFFFFFFFu, s, 2);
        s += __shfl_xor_sync(0xFFFFFFFFu, s, 4);
        if (m8 == 0) {
            s += blv;
            out[(size_t)gbat * TTOT + t] = s;
            XCw[lb] = pack1(((t + 1) < TOBS) ? xnext : s);
        }
        __syncwarp();
    }
}

extern "C" void kernel_launch(void* const* d_in, const int* in_sizes, int n_in,
                              void* d_out, int out_size)
{
    (void)in_sizes; (void)n_in; (void)out_size;
    const float* x    = (const float*)d_in[0];
    const float* wih0 = (const float*)d_in[1];
    const float* whh0 = (const float*)d_in[2];
    const float* bih0 = (const float*)d_in[3];
    const float* bhh0 = (const float*)d_in[4];
    const float* wih1 = (const float*)d_in[5];
    const float* whh1 = (const float*)d_in[6];
    const float* bih1 = (const float*)d_in[7];
    const float* bhh1 = (const float*)d_in[8];
    const float* wlin = (const float*)d_in[9];
    const float* blin = (const float*)d_in[10];
    float* out = (float*)d_out;

    cudaFuncSetAttribute(lstm576_wi2_kernel,
                         cudaFuncAttributeMaxDynamicSharedMemorySize, SMEM_BYTES);
    lstm576_wi2_kernel<<<NCTA, NTHR, SMEM_BYTES>>>(
        x, wih0, whh0, bih0, bhh0, wih1, whh1, bih1, bhh1, wlin, blin, out);
}

// round 9
// speedup vs baseline: 1.1444x; 1.1444x over previous
#include <cuda_runtime.h>

// Modelev12: 2-layer LSTM, H=48, B=4096, T=512, F=64
// R8: 2-warp independent pairs with named barriers.
//  - pair p owns 8 batches; warp A rows 0..95, warp B rows 96..191
//  - f32x2 packed over batch: scalar LDS.32 weights (1 wf), broadcast LDS.128 h
//  - weight bytes/SM/step halved vs warp-independent R6 (B=4 effective)
#define H      48
#define TOBS   512
#define FPRED  64
#define TTOT   (TOBS + FPRED)     // 576
#define BATCH  4096
#define MB     32                 // batch rows per CTA
#define NCTA   (BATCH / MB)       // 128
#define NTHR   256                // 8 warps = 4 pairs x 2 row-halves

typedef unsigned long long ull;

// float offsets
#define OFF_WT0 0                        // [48][192]  Whh0^T scalar
#define OFF_WT1 (OFF_WT0 + 48*192)       // [96][192]  [Wih1|Whh1]^T scalar
#define OFF_WI0 (OFF_WT1 + 96*192)       // [192]
#define OFF_B0  (OFF_WI0 + 192)          // [192]
#define OFF_B1  (OFF_B0 + 192)           // [192]
#define OFF_WL  (OFF_B1 + 192)           // [48]
#define OFF_HC  (OFF_WL + 48)            // 4 pairs x [96][8]  h (non-dup, batch-major)
#define OFF_XC  (OFF_HC + 4*768)         // 4 pairs x [8]
#define OFF_GT  (OFF_XC + 4*8)           // 4 pairs x [192][10] gates (stride 10)
#define GSTR    10
#define SMEM_FLOATS (OFF_GT + 4*192*GSTR)
#define SMEM_BYTES  (SMEM_FLOATS * 4)    // ~156 KB

__device__ __forceinline__ ull ffma2(ull a, ull b, ull c) {
    ull d;
    asm("fma.rn.f32x2 %0, %1, %2, %3;" : "=l"(d) : "l"(a), "l"(b), "l"(c));
    return d;
}
__device__ __forceinline__ ull pack1(float v) {            // {v, v}
    ull d; asm("mov.b64 %0, {%1, %1};" : "=l"(d) : "f"(v)); return d;
}
__device__ __forceinline__ float fsig(float xv) {
    float e = __expf(-xv);
    return __fdividef(1.0f, 1.0f + e);
}
__device__ __forceinline__ float ftanh(float xv) {
    float a = fabsf(xv);
    float e = __expf(-2.0f * a);
    float r = __fdividef(1.0f - e, 1.0f + e);
    return copysignf(r, xv);
}
// named barrier: 64 threads of warp-pair `id+1`
#define PBAR(id) asm volatile("bar.sync %0, 64;" :: "r"((id) + 1) : "memory")

__global__ void __launch_bounds__(NTHR, 1) lstm576_pair_kernel(
    const float* __restrict__ x,
    const float* __restrict__ wih0, const float* __restrict__ whh0,
    const float* __restrict__ bih0, const float* __restrict__ bhh0,
    const float* __restrict__ wih1, const float* __restrict__ whh1,
    const float* __restrict__ bih1, const float* __restrict__ bhh1,
    const float* __restrict__ wlin, const float* __restrict__ blin,
    float* __restrict__ out)
{
    extern __shared__ float sm[];
    float* WT0 = sm + OFF_WT0;
    float* WT1 = sm + OFF_WT1;
    float* WI0 = sm + OFF_WI0;
    float* B0s = sm + OFF_B0;
    float* B1s = sm + OFF_B1;

    const int tid  = threadIdx.x;
    const int lane = tid & 31;
    const int w    = tid >> 5;        // 0..7
    const int pr   = w >> 1;          // pair 0..3
    const int wh   = w & 1;           // row half: 0 -> rows 0..95, 1 -> 96..191
    const int rr   = 96 * wh + lane;  // this lane's rows: rr, rr+32, rr+64
    const int m8   = lane & 7;
    const int bl   = 4 * wh + (lane >> 3);     // local batch (0..7) for act/head
    const int gb0  = blockIdx.x * MB;
    const int gbat = gb0 + 8 * pr + bl;        // global batch for act/head

    float* HCp = sm + OFF_HC + pr * 768;       // [96][8]
    float* XCp = sm + OFF_XC + pr * 8;         // [8]
    float* GTp = sm + OFF_GT + pr * 192 * GSTR;

    // ---- one-time staging (scalar transposed weights) ----
    for (int i = tid; i < 48 * 192; i += NTHR) {
        int k = i / 192, r = i - k * 192;
        WT0[i] = whh0[r * 48 + k];
    }
    for (int i = tid; i < 96 * 192; i += NTHR) {
        int k = i / 192, r = i - k * 192;
        WT1[i] = (k < 48) ? wih1[r * 48 + k] : whh1[r * 48 + (k - 48)];
    }
    for (int i = tid; i < 192; i += NTHR) {
        WI0[i] = wih0[i];
        B0s[i] = bih0[i] + bhh0[i];
        B1s[i] = bih1[i] + bhh1[i];
    }
    for (int i = tid; i < 4 * 768; i += NTHR) sm[OFF_HC + i] = 0.0f;
    if (tid < MB) sm[OFF_XC + tid] = x[(size_t)(gb0 + tid) * TOBS];
    const float blv = blin[0];

    float wlr[6];
#pragma unroll
    for (int i = 0; i < 6; i++) wlr[i] = wlin[m8 * 6 + i];

    float c0r[6], c1r[6];
#pragma unroll
    for (int i = 0; i < 6; i++) { c0r[i] = 0.0f; c1r[i] = 0.0f; }

    __syncthreads();   // weights staged (only block-wide sync)

    ull acc[3][4];     // [row m][batch pair bp]

    for (int t = 0; t < TTOT; t++) {
        float xnext = 0.0f;
        if (m8 == 0 && (t + 1) < TOBS)
            xnext = x[(size_t)gbat * TOBS + (t + 1)];

        // ============ layer 0: rows rr+32m, k = x + h0[0..47] ============
        {
            ull x2[4];
#pragma unroll
            for (int bp = 0; bp < 4; bp++)
                x2[bp] = *(const ull*)(XCp + 2 * bp);        // broadcast LDS.64
#pragma unroll
            for (int m = 0; m < 3; m++) {
                ull wi = pack1(WI0[rr + 32 * m]);
                ull bs = pack1(B0s[rr + 32 * m]);
#pragma unroll
                for (int bp = 0; bp < 4; bp++)
                    acc[m][bp] = ffma2(wi, x2[bp], bs);
            }
#pragma unroll 4
            for (int kt = 0; kt < 48; kt += 2) {
                const ulonglong2* hp = (const ulonglong2*)(HCp + kt * 8);
                ulonglong2 hA = hp[0];   // k:   b0-3 (2 packed pairs)
                ulonglong2 hB = hp[1];   // k:   b4-7
                ulonglong2 hC = hp[2];   // k+1: b0-3
                ulonglong2 hD = hp[3];   // k+1: b4-7
                float wa[3], wb[3];
#pragma unroll
                for (int m = 0; m < 3; m++) {
                    wa[m] = WT0[kt * 192 + rr + 32 * m];
                    wb[m] = WT0[(kt + 1) * 192 + rr + 32 * m];
                }
#pragma unroll
                for (int m = 0; m < 3; m++) {
                    ull w2 = pack1(wa[m]);
                    acc[m][0] = ffma2(w2, hA.x, acc[m][0]);
                    acc[m][1] = ffma2(w2, hA.y, acc[m][1]);
                    acc[m][2] = ffma2(w2, hB.x, acc[m][2]);
                    acc[m][3] = ffma2(w2, hB.y, acc[m][3]);
                }
#pragma unroll
                for (int m = 0; m < 3; m++) {
                    ull w2 = pack1(wb[m]);
                    acc[m][0] = ffma2(w2, hC.x, acc[m][0]);
                    acc[m][1] = ffma2(w2, hC.y, acc[m][1]);
                    acc[m][2] = ffma2(w2, hD.x, acc[m][2]);
                    acc[m][3] = ffma2(w2, hD.y, acc[m][3]);
                }
            }
#pragma unroll
            for (int m = 0; m < 3; m++)
#pragma unroll
                for (int bp = 0; bp < 4; bp++)
                    *(ull*)(GTp + (rr + 32 * m) * GSTR + 2 * bp) = acc[m][bp];
        }
        PBAR(pr);

        // ---- layer 0 activations: this warp's 4 batches (b = bl), all j ----
#pragma unroll
        for (int i = 0; i < 6; i++) {
            int j = m8 * 6 + i;
            const float* g = GTp + j * GSTR + bl;
            float ii = fsig(g[0 * 48 * GSTR]);
            float ff = fsig(g[1 * 48 * GSTR]);
            float gg = ftanh(g[2 * 48 * GSTR]);
            float oo = fsig(g[3 * 48 * GSTR]);
            float c = fmaf(ff, c0r[i], ii * gg);
            c0r[i] = c;
            HCp[j * 8 + bl] = oo * ftanh(c);
        }
        PBAR(pr);

        // ============ layer 1: k over h0(0..47) + h1(48..95) ============
        {
#pragma unroll
            for (int m = 0; m < 3; m++) {
                ull bs = pack1(B1s[rr + 32 * m]);
#pragma unroll
                for (int bp = 0; bp < 4; bp++) acc[m][bp] = bs;
            }
#pragma unroll 4
            for (int kt = 0; kt < 96; kt += 2) {
                const ulonglong2* hp = (const ulonglong2*)(HCp + kt * 8);
                ulonglong2 hA = hp[0];
                ulonglong2 hB = hp[1];
                ulonglong2 hC = hp[2];
                ulonglong2 hD = hp[3];
                float wa[3], wb[3];
#pragma unroll
                for (int m = 0; m < 3; m++) {
                    wa[m] = WT1[kt * 192 + rr + 32 * m];
                    wb[m] = WT1[(kt + 1) * 192 + rr + 32 * m];
                }
#pragma unroll
                for (int m = 0; m < 3; m++) {
                    ull w2 = pack1(wa[m]);
                    acc[m][0] = ffma2(w2, hA.x, acc[m][0]);
                    acc[m][1] = ffma2(w2, hA.y, acc[m][1]);
                    acc[m][2] = ffma2(w2, hB.x, acc[m][2]);
                    acc[m][3] = ffma2(w2, hB.y, acc[m][3]);
                }
#pragma unroll
                for (int m = 0; m < 3; m++) {
                    ull w2 = pack1(wb[m]);
                    acc[m][0] = ffma2(w2, hC.x, acc[m][0]);
                    acc[m][1] = ffma2(w2, hC.y, acc[m][1]);
                    acc[m][2] = ffma2(w2, hD.x, acc[m][2]);
                    acc[m][3] = ffma2(w2, hD.y, acc[m][3]);
                }
            }
#pragma unroll
            for (int m = 0; m < 3; m++)
#pragma unroll
                for (int bp = 0; bp < 4; bp++)
                    *(ull*)(GTp + (rr + 32 * m) * GSTR + 2 * bp) = acc[m][bp];
        }
        PBAR(pr);

        // ---- layer 1 activations + fused head ----
        float s = 0.0f;
#pragma unroll
        for (int i = 0; i < 6; i++) {
            int j = m8 * 6 + i;
            const float* g = GTp + j * GSTR + bl;
            float ii = fsig(g[0 * 48 * GSTR]);
            float ff = fsig(g[1 * 48 * GSTR]);
            float gg = ftanh(g[2 * 48 * GSTR]);
            float oo = fsig(g[3 * 48 * GSTR]);
            float c = fmaf(ff, c1r[i], ii * gg);
            c1r[i] = c;
            float h = oo * ftanh(c);
            HCp[(48 + j) * 8 + bl] = h;
            s = fmaf(h, wlr[i], s);
        }
        s += __shfl_xor_sync(0xFFFFFFFFu, s, 1);
        s += __shfl_xor_sync(0xFFFFFFFFu, s, 2);
        s += __shfl_xor_sync(0xFFFFFFFFu, s, 4);
        if (m8 == 0) {
            s += blv;
            out[(size_t)gbat * TTOT + t] = s;
            XCp[bl] = ((t + 1) < TOBS) ? xnext : s;
        }
        PBAR(pr);
    }
}

extern "C" void kernel_launch(void* const* d_in, const int* in_sizes, int n_in,
                              void* d_out, int out_size)
{
    (void)in_sizes; (void)n_in; (void)out_size;
    const float* x    = (const float*)d_in[0];
    const float* wih0 = (const float*)d_in[1];
    const float* whh0 = (const float*)d_in[2];
    const float* bih0 = (const float*)d_in[3];
    const float* bhh0 = (const float*)d_in[4];
    const float* wih1 = (const float*)d_in[5];
    const float* whh1 = (const float*)d_in[6];
    const float* bih1 = (const float*)d_in[7];
    const float* bhh1 = (const float*)d_in[8];
    const float* wlin = (const float*)d_in[9];
    const float* blin = (const float*)d_in[10];
    float* out = (float*)d_out;

    cudaFuncSetAttribute(lstm576_pair_kernel,
                         cudaFuncAttributeMaxDynamicSharedMemorySize, SMEM_BYTES);
    lstm576_pair_kernel<<<NCTA, NTHR, SMEM_BYTES>>>(
        x, wih0, whh0, bih0, bhh0, wih1, whh1, bih1, bhh1, wlin, blin, out);
}

// round 10
// speedup vs baseline: 1.2420x; 1.0853x over previous
#include <cuda_runtime.h>

// Modelev12: 2-layer LSTM, H=48, B=4096, T=512, F=64
// R9 = R6 (best, warp-independent islands) + anti-phase warp skew + unroll 4.
//  - warps 4..7 (one per SMSP) delayed ~half a step once, so the two warps on
//    each SMSP stay phase-offset: MUFU act phases overlap FMA matvec phases.
//  - no arithmetic changes vs R6.
#define H      48
#define TOBS   512
#define FPRED  64
#define TTOT   (TOBS + FPRED)     // 576
#define BATCH  4096
#define MB     32                 // batch rows per CTA
#define NCTA   (BATCH / MB)       // 128
#define NTHR   256                // 8 warps x 4 batches each
#define NSKEW  1400               // ~5.6K cycles (IMAD chain, lat 4)

typedef unsigned long long ull;

__device__ unsigned int g_skew_sink[NCTA * NTHR];   // unelidable skew sink

// float-offset shared layout (ull regions at even float offsets)
#define OFF_WTP0 0                       // ull[48*96]  {Whh0[q][k], Whh0[q+96][k]}
#define OFF_WTP1 9216                    // ull[96*96]  layer-1 row-paired
#define OFF_WI0P 27648                   // ull[96]
#define OFF_B0P  27840                   // ull[96]
#define OFF_B1P  28032                   // ull[96]
#define OFF_HW   28224                   // 8 warps x [96k][4b] floats (384 each)
#define OFF_XCW  31296                   // 8 warps x 8 floats
#define OFF_GTP  31360                   // 8 warps x 4*GSTR ull
#define GSTR     101                     // ull stride per batch in gate buffer
#define GWARP    (4 * GSTR)
#define SMEM_FLOATS (OFF_GTP + 8 * 2 * GWARP)
#define SMEM_BYTES  (SMEM_FLOATS * 4)

__device__ __forceinline__ ull ffma2(ull a, ull b, ull c) {
    ull d;
    asm("fma.rn.f32x2 %0, %1, %2, %3;" : "=l"(d) : "l"(a), "l"(b), "l"(c));
    return d;
}
__device__ __forceinline__ ull pack1(float v) {            // {v, v}
    ull d; asm("mov.b64 %0, {%1, %1};" : "=l"(d) : "f"(v)); return d;
}
__device__ __forceinline__ ull pack2(float lo, float hi) {
    ull d; asm("mov.b64 %0, {%1, %2};" : "=l"(d) : "f"(lo), "f"(hi)); return d;
}
__device__ __forceinline__ float fsig(float xv) {
    float e = __expf(-xv);
    return __fdividef(1.0f, 1.0f + e);
}
__device__ __forceinline__ float ftanh(float xv) {
    float a = fabsf(xv);
    float e = __expf(-2.0f * a);
    float r = __fdividef(1.0f - e, 1.0f + e);
    return copysignf(r, xv);
}

__global__ void __launch_bounds__(NTHR, 1) lstm576_wi_skew_kernel(
    const float* __restrict__ x,
    const float* __restrict__ wih0, const float* __restrict__ whh0,
    const float* __restrict__ bih0, const float* __restrict__ bhh0,
    const float* __restrict__ wih1, const float* __restrict__ whh1,
    const float* __restrict__ bih1, const float* __restrict__ bhh1,
    const float* __restrict__ wlin, const float* __restrict__ blin,
    float* __restrict__ out)
{
    extern __shared__ float sm[];
    ull* WTP0 = (ull*)(sm + OFF_WTP0);
    ull* WTP1 = (ull*)(sm + OFF_WTP1);
    ull* WI0P = (ull*)(sm + OFF_WI0P);
    ull* B0P  = (ull*)(sm + OFF_B0P);
    ull* B1P  = (ull*)(sm + OFF_B1P);

    const int tid  = threadIdx.x;
    const int lane = tid & 31;
    const int w    = tid >> 5;           // warp 0..7
    const int m8   = lane & 7;           // 8-lane segment position
    const int lb   = lane >> 3;          // local batch 0..3 (act/head)
    const int gb0  = blockIdx.x * MB;
    const int gbat = gb0 + 4 * w + lb;

    float* HWw  = sm + OFF_HW  + w * 384;            // [96][4] h state
    float* XCw  = sm + OFF_XCW + w * 8;              // 4 inputs
    ull*   GTPw = (ull*)(sm + OFF_GTP) + w * GWARP;  // [4][GSTR] gate pairs

    // ---- one-time staging ----
    for (int i = tid; i < 48 * 96; i += NTHR) {
        int k = i / 96, q = i - k * 96;
        WTP0[i] = pack2(whh0[q * 48 + k], whh0[(q + 96) * 48 + k]);
    }
    for (int i = tid; i < 96 * 96; i += NTHR) {
        int k = i / 96, q = i - k * 96;
        float v0 = (k < 48) ? wih1[q * 48 + k] : whh1[q * 48 + (k - 48)];
        float v1 = (k < 48) ? wih1[(q + 96) * 48 + k] : whh1[(q + 96) * 48 + (k - 48)];
        WTP1[i] = pack2(v0, v1);
    }
    if (tid < 96) {
        WI0P[tid] = pack2(wih0[tid], wih0[tid + 96]);
        B0P[tid]  = pack2(bih0[tid] + bhh0[tid], bih0[tid + 96] + bhh0[tid + 96]);
        B1P[tid]  = pack2(bih1[tid] + bhh1[tid], bih1[tid + 96] + bhh1[tid + 96]);
    }
    for (int i = tid; i < 8 * 384; i += NTHR) sm[OFF_HW + i] = 0.0f;
    if (m8 == 0) XCw[lb] = x[(size_t)gbat * TOBS];
    const float blv = blin[0];

    float wlr[6];
#pragma unroll
    for (int i = 0; i < 6; i++) wlr[i] = wlin[m8 * 6 + i];

    float c0r[6], c1r[6];
#pragma unroll
    for (int i = 0; i < 6; i++) { c0r[i] = 0.0f; c1r[i] = 0.0f; }

    __syncthreads();   // only block-wide sync: weights staged

    // ---- anti-phase skew: one warp per SMSP delayed ~half a step ----
    if (w >= 4) {
        unsigned int v = (unsigned int)(tid * 2654435761u + blockIdx.x);
#pragma unroll 1
        for (int i = 0; i < NSKEW; i++)
            v = v * 1664525u + 1013904223u;      // dependent IMAD chain
        g_skew_sink[blockIdx.x * NTHR + tid] = v; // unelidable, deterministic
    }

    ull acc[3][4];

    for (int t = 0; t < TTOT; t++) {
        float xnext = 0.0f;
        if (m8 == 0 && (t + 1) < TOBS)
            xnext = x[(size_t)gbat * TOBS + (t + 1)];

        // ============ layer 0 matvec: 192 rows x (x + 48 h0) ============
        {
            float4 x4 = *(const float4*)XCw;
            ull xx[4] = { pack1(x4.x), pack1(x4.y), pack1(x4.z), pack1(x4.w) };
#pragma unroll
            for (int pp = 0; pp < 3; pp++) {
                ull wi = WI0P[32 * pp + lane];
                ull bs = B0P[32 * pp + lane];
#pragma unroll
                for (int b = 0; b < 4; b++) acc[pp][b] = ffma2(wi, xx[b], bs);
            }
#pragma unroll 4
            for (int kt = 0; kt < 48; kt += 4) {
                float4 hq[4];
#pragma unroll
                for (int d = 0; d < 4; d++)
                    hq[d] = *(const float4*)(HWw + (kt + d) * 4);
#pragma unroll
                for (int d = 0; d < 4; d++) {
                    ull w2[3];
#pragma unroll
                    for (int pp = 0; pp < 3; pp++)
                        w2[pp] = WTP0[(kt + d) * 96 + 32 * pp + lane];
                    ull hh[4] = { pack1(hq[d].x), pack1(hq[d].y),
                                  pack1(hq[d].z), pack1(hq[d].w) };
#pragma unroll
                    for (int pp = 0; pp < 3; pp++)
#pragma unroll
                        for (int b = 0; b < 4; b++)
                            acc[pp][b] = ffma2(w2[pp], hh[b], acc[pp][b]);
                }
            }
#pragma unroll
            for (int pp = 0; pp < 3; pp++)
#pragma unroll
                for (int b = 0; b < 4; b++)
                    GTPw[b * GSTR + 32 * pp + lane] = acc[pp][b];
        }
        __syncwarp();

        // ---- layer 0 activations: pair j = (i_j, g_j), pair j+48 = (f_j, o_j) ----
#pragma unroll
        for (int i = 0; i < 6; i++) {
            int j = m8 * 6 + i;
            float2 ig = *(const float2*)(GTPw + lb * GSTR + j);
            float2 fo = *(const float2*)(GTPw + lb * GSTR + 48 + j);
            float ii = fsig(ig.x), gg = ftanh(ig.y);
            float ff = fsig(fo.x), oo = fsig(fo.y);
            float c = fmaf(ff, c0r[i], ii * gg);
            c0r[i] = c;
            HWw[j * 4 + lb] = oo * ftanh(c);
        }
        __syncwarp();

        // ============ layer 1 matvec: 192 rows x (48 h0_new + 48 h1_old) ============
        {
#pragma unroll
            for (int pp = 0; pp < 3; pp++) {
                ull bs = B1P[32 * pp + lane];
#pragma unroll
                for (int b = 0; b < 4; b++) acc[pp][b] = bs;
            }
#pragma unroll 4
            for (int kt = 0; kt < 96; kt += 4) {
                float4 hq[4];
#pragma unroll
                for (int d = 0; d < 4; d++)
                    hq[d] = *(const float4*)(HWw + (kt + d) * 4);
#pragma unroll
                for (int d = 0; d < 4; d++) {
                    ull w2[3];
#pragma unroll
                    for (int pp = 0; pp < 3; pp++)
                        w2[pp] = WTP1[(kt + d) * 96 + 32 * pp + lane];
                    ull hh[4] = { pack1(hq[d].x), pack1(hq[d].y),
                                  pack1(hq[d].z), pack1(hq[d].w) };
#pragma unroll
                    for (int pp = 0; pp < 3; pp++)
#pragma unroll
                        for (int b = 0; b < 4; b++)
                            acc[pp][b] = ffma2(w2[pp], hh[b], acc[pp][b]);
                }
            }
#pragma unroll
            for (int pp = 0; pp < 3; pp++)
#pragma unroll
                for (int b = 0; b < 4; b++)
                    GTPw[b * GSTR + 32 * pp + lane] = acc[pp][b];
        }
        __syncwarp();

        // ---- layer 1 activations + fused in-warp head ----
        float s = 0.0f;
#pragma unroll
        for (int i = 0; i < 6; i++) {
            int j = m8 * 6 + i;
            float2 ig = *(const float2*)(GTPw + lb * GSTR + j);
            float2 fo = *(const float2*)(GTPw + lb * GSTR + 48 + j);
            float ii = fsig(ig.x), gg = ftanh(ig.y);
            float ff = fsig(fo.x), oo = fsig(fo.y);
            float c = fmaf(ff, c1r[i], ii * gg);
            c1r[i] = c;
            float h = oo * ftanh(c);
            HWw[(48 + j) * 4 + lb] = h;
            s = fmaf(h, wlr[i], s);
        }
        s += __shfl_xor_sync(0xFFFFFFFFu, s, 1);
        s += __shfl_xor_sync(0xFFFFFFFFu, s, 2);
        s += __shfl_xor_sync(0xFFFFFFFFu, s, 4);
        if (m8 == 0) {
            s += blv;
            out[(size_t)gbat * TTOT + t] = s;
            XCw[lb] = ((t + 1) < TOBS) ? xnext : s;
        }
        __syncwarp();
    }
}

extern "C" void kernel_launch(void* const* d_in, const int* in_sizes, int n_in,
                              void* d_out, int out_size)
{
    (void)in_sizes; (void)n_in; (void)out_size;
    const float* x    = (const float*)d_in[0];
    const float* wih0 = (const float*)d_in[1];
    const float* whh0 = (const float*)d_in[2];
    const float* bih0 = (const float*)d_in[3];
    const float* bhh0 = (const float*)d_in[4];
    const float* wih1 = (const float*)d_in[5];
    const float* whh1 = (const float*)d_in[6];
    const float* bih1 = (const float*)d_in[7];
    const float* bhh1 = (const float*)d_in[8];
    const float* wlin = (const float*)d_in[9];
    const float* blin = (const float*)d_in[10];
    float* out = (float*)d_out;

    cudaFuncSetAttribute(lstm576_wi_skew_kernel,
                         cudaFuncAttributeMaxDynamicSharedMemorySize, SMEM_BYTES);
    lstm576_wi_skew_kernel<<<NCTA, NTHR, SMEM_BYTES>>>(
        x, wih0, whh0, bih0, bhh0, wih1, whh1, bih1, bhh1, wlin, blin, out);
}